// round 14
// baseline (speedup 1.0000x reference)
#include <cuda_runtime.h>
#include <cuda_fp16.h>
#include <cstdint>

// ---------------------------------------------------------------------------
// Problem constants
// ---------------------------------------------------------------------------
#define U_NODES 200000
#define F_DIM   256
#define E_DIM   128
#define B_ROWS  20000
#define K_SAMP  33
#define BN_EPS  1e-5f

#define TM      128
#define NTILES  ((U_NODES + TM - 1) / TM) // 1563

// SMEM layout (bytes, dynamic)
#define OFF_BIAS   0                          // 512 B
#define OFF_W      512                        // 64 KB (fp16 W, whole K)
#define OFF_RED    (OFF_W + 65536)            // 8 KB stats reduction
#define SMEM_TOTAL (OFF_RED + 8192)           // 74240 -> 2 CTAs/SM

// ---------------------------------------------------------------------------
// Device scratch
// ---------------------------------------------------------------------------
__device__ __half g_h[(size_t)U_NODES * E_DIM];      // h in fp16 (51.2 MB)
__device__ float g_part[NTILES * 2 * E_DIM];
__device__ __align__(16) float g_ab[2 * E_DIM];
// W image: [K=256 rows][N=128] fp16 (256B rows), 16B-col XOR-swizzle by (k&7)
__device__ __align__(16) __half g_wh[F_DIM * E_DIM];

// ---------------------------------------------------------------------------
// Helpers
// ---------------------------------------------------------------------------
__device__ __forceinline__ uint32_t smem_u32(const void* p) {
    uint32_t a;
    asm("{ .reg .u64 t; cvta.to.shared.u64 t, %1; cvt.u32.u64 %0, t; }"
        : "=r"(a) : "l"(p));
    return a;
}
__device__ __forceinline__ void cp16(uint32_t s, const void* g) {
    asm volatile("cp.async.cg.shared.global [%0], [%1], 16;"
                 :: "r"(s), "l"(g) : "memory");
}
__device__ __forceinline__ void cp_commit() {
    asm volatile("cp.async.commit_group;" ::: "memory");
}
__device__ __forceinline__ void cp_wait0() {
    asm volatile("cp.async.wait_group 0;" ::: "memory");
}
__device__ __forceinline__ void ldmx4t(uint32_t addr, uint32_t* r) {
    asm volatile("ldmatrix.sync.aligned.m8n8.x4.trans.shared.b16 {%0,%1,%2,%3}, [%4];"
                 : "=r"(r[0]), "=r"(r[1]), "=r"(r[2]), "=r"(r[3]) : "r"(addr));
}
__device__ __forceinline__ void mma_f16(float* d, const uint32_t* a,
                                        uint32_t b0, uint32_t b1) {
    asm volatile(
        "mma.sync.aligned.m16n8k16.row.col.f32.f16.f16.f32 "
        "{%0,%1,%2,%3}, {%4,%5,%6,%7}, {%8,%9}, {%0,%1,%2,%3};"
        : "+f"(d[0]), "+f"(d[1]), "+f"(d[2]), "+f"(d[3])
        : "r"(a[0]), "r"(a[1]), "r"(a[2]), "r"(a[3]), "r"(b0), "r"(b1));
}
__device__ __forceinline__ uint32_t pack_f16x2(float lo, float hi) {
    uint32_t r;
    asm("cvt.rn.f16x2.f32 %0, %1, %2;" : "=r"(r) : "f"(hi), "f"(lo));
    return r;
}

// ---------------------------------------------------------------------------
// Kernel 0: W [256,128] fp32 -> fp16, [K][N] row-major, swizzled.
// byte offset = k*256 + ((n*2) ^ ((k&7)<<4))
// ---------------------------------------------------------------------------
__global__ void prep_w_kernel(const float* __restrict__ W) {
    int idx = blockIdx.x * 256 + threadIdx.x;    // 0..32767
    int k = idx >> 7;
    int n = idx & 127;
    uint32_t off = (uint32_t)k * 256 + (((uint32_t)n * 2) ^ ((k & 7) << 4));
    g_wh[off >> 1] = __float2half_rn(W[idx]);
}

// ---------------------------------------------------------------------------
// Kernel 1: h = A @ W + b, SYNC-FREE mainloop.
// 256 threads = 8 warps, each warp owns 16 rows x 128 cols (no A sharing).
// A loaded DIRECTLY into mma fragment regs (LDG.64 coalesced), W resident
// in smem via ldmatrix.trans. No producer / A smem / main-loop syncs.
// R13 bug fixed: W column byte offset was double-scaled for lanes 16-31
// (read past the W buffer -> NaN). Correct: ncol = nb16*32 + (lane>>4)*16.
// ---------------------------------------------------------------------------
__global__ void __launch_bounds__(256, 2)
gemm_mma_kernel(const float* __restrict__ A, const float* __restrict__ bias)
{
    extern __shared__ char smem[];
    const uint32_t sm = smem_u32(smem);
    const int tid  = threadIdx.x;
    const int wid  = tid >> 5;            // 0..7 -> 16-row band
    const int lane = tid & 31;
    const int row0 = blockIdx.x * TM;

    float* sbias = (float*)(smem + OFF_BIAS);
    if (tid < 128) sbias[tid] = bias[tid];

    // ---- load full W (64KB fp16) once via cp.async ----
    {
        const char* src = (const char*)g_wh;
        const uint32_t dst = sm + OFF_W;
#pragma unroll
        for (int j = 0; j < 16; j++) {
            const int u = tid + j * 256;          // 16B units, 0..4095
            cp16(dst + u * 16, src + (size_t)u * 16);
        }
        cp_commit();
    }

    // ---- A fragment addressing (m16n8k16 A layout, row-major) ----
    // lane holds rows {r0, r0+8}, k-cols {2c, 2c+1, 2c+8, 2c+9}, c = lane&3
    const int r0 = row0 + wid * 16 + (lane >> 2);
    const int r1 = r0 + 8;
    const bool v0 = r0 < U_NODES;
    const bool v1 = r1 < U_NODES;
    const float* a0p = A + (size_t)r0 * F_DIM + (lane & 3) * 2;
    const float* a1p = A + (size_t)r1 * F_DIM + (lane & 3) * 2;

    // ---- W fragment addressing (R9 formulas) ----
    const int bk = lane & 15;
    const uint32_t brow = (uint32_t)bk * 256;
    const uint32_t bxor = (uint32_t)(bk & 7) << 4;
    const uint32_t bhalf = (uint32_t)(lane >> 4) * 16;   // bytes (8 cols)

    float acc[16][4];
#pragma unroll
    for (int nb = 0; nb < 16; nb++)
#pragma unroll
        for (int q = 0; q < 4; q++) acc[nb][q] = 0.f;

    cp_wait0();
    __syncthreads();                      // W resident

    const uint32_t Wb = sm + OFF_W;
    const float2 z2 = make_float2(0.f, 0.f);

    // pipeline: A floats for k-step ks+1 loaded while computing ks
    float2 nx0, nx1, nx2, nx3;
    nx0 = v0 ? __ldg((const float2*)(a0p))     : z2;
    nx1 = v1 ? __ldg((const float2*)(a1p))     : z2;
    nx2 = v0 ? __ldg((const float2*)(a0p + 8)) : z2;
    nx3 = v1 ? __ldg((const float2*)(a1p + 8)) : z2;

#pragma unroll
    for (int ks = 0; ks < 16; ks++) {
        uint32_t af[4];
        af[0] = pack_f16x2(nx0.x, nx0.y);
        af[1] = pack_f16x2(nx1.x, nx1.y);
        af[2] = pack_f16x2(nx2.x, nx2.y);
        af[3] = pack_f16x2(nx3.x, nx3.y);
        if (ks < 15) {
            const int o = (ks + 1) * 16;
            nx0 = v0 ? __ldg((const float2*)(a0p + o))     : z2;
            nx1 = v1 ? __ldg((const float2*)(a1p + o))     : z2;
            nx2 = v0 ? __ldg((const float2*)(a0p + o + 8)) : z2;
            nx3 = v1 ? __ldg((const float2*)(a1p + o + 8)) : z2;
        }
        const uint32_t wrow = Wb + (uint32_t)ks * 4096 + brow;
#pragma unroll
        for (int h = 0; h < 2; h++) {       // 2 halves of 4 col-groups
            uint32_t bh[4][4];
#pragma unroll
            for (int j = 0; j < 4; j++) {
                // col group nb16 = h*4+j covers 16 cols = 32 bytes
                const uint32_t ncol = ((uint32_t)(h * 4 + j) * 32 + bhalf)
                                      ^ bxor;
                ldmx4t(wrow + ncol, bh[j]);
            }
#pragma unroll
            for (int j = 0; j < 4; j++) {
                const int nb = h * 4 + j;
                mma_f16(acc[nb * 2],     af, bh[j][0], bh[j][1]);
                mma_f16(acc[nb * 2 + 1], af, bh[j][2], bh[j][3]);
            }
        }
    }

    // ---- epilogue: per-group store + stats ----
    float* red_s = (float*)(smem + OFF_RED);        // [8][128]
    float* red_q = red_s + 1024;
    const int cbase = (lane & 3) * 2;
#pragma unroll
    for (int nb = 0; nb < 16; nb++) {
        const int col = nb * 8 + cbase;
        const float be0 = sbias[col];
        const float be1 = sbias[col + 1];
        const float x0 = v0 ? acc[nb][0] + be0 : 0.f;
        const float x1 = v0 ? acc[nb][1] + be1 : 0.f;
        const float x2 = v1 ? acc[nb][2] + be0 : 0.f;
        const float x3 = v1 ? acc[nb][3] + be1 : 0.f;
        if (v0) *(uint32_t*)(g_h + (size_t)r0 * E_DIM + col) = pack_f16x2(x0, x1);
        if (v1) *(uint32_t*)(g_h + (size_t)r1 * E_DIM + col) = pack_f16x2(x2, x3);
        float s0 = x0 + x2, s1 = x1 + x3;
        float q0 = x0 * x0 + x2 * x2, q1 = x1 * x1 + x3 * x3;
#pragma unroll
        for (int m = 4; m <= 16; m <<= 1) {
            s0 += __shfl_xor_sync(0xFFFFFFFFu, s0, m);
            s1 += __shfl_xor_sync(0xFFFFFFFFu, s1, m);
            q0 += __shfl_xor_sync(0xFFFFFFFFu, q0, m);
            q1 += __shfl_xor_sync(0xFFFFFFFFu, q1, m);
        }
        if (lane < 4) {
            red_s[wid * 128 + nb * 8 + lane * 2]     = s0;
            red_s[wid * 128 + nb * 8 + lane * 2 + 1] = s1;
            red_q[wid * 128 + nb * 8 + lane * 2]     = q0;
            red_q[wid * 128 + nb * 8 + lane * 2 + 1] = q1;
        }
    }
    __syncthreads();
    if (tid < 128) {
        float ts = 0.f, tq = 0.f;
#pragma unroll
        for (int w = 0; w < 8; w++) {
            ts += red_s[w * 128 + tid];
            tq += red_q[w * 128 + tid];
        }
        g_part[blockIdx.x * 256 + tid]       = ts;
        g_part[blockIdx.x * 256 + 128 + tid] = tq;
    }
}

// ---------------------------------------------------------------------------
// Kernel 2: finalize BN stats (one block per embedding column)
// ---------------------------------------------------------------------------
__global__ void finalize_stats_kernel(const float* __restrict__ gamma,
                                      const float* __restrict__ beta)
{
    __shared__ float ss[256], sq[256];
    const int e = blockIdx.x;
    const int t = threadIdx.x;
    float s = 0.f, q = 0.f;
    for (int i = t; i < NTILES; i += 256) {
        s += g_part[i * 256 + e];
        q += g_part[i * 256 + 128 + e];
    }
    ss[t] = s; sq[t] = q;
    __syncthreads();
    for (int st = 128; st > 0; st >>= 1) {
        if (t < st) { ss[t] += ss[t + st]; sq[t] += sq[t + st]; }
        __syncthreads();
    }
    if (t == 0) {
        const float mu  = ss[0] * (1.0f / U_NODES);
        const float var = sq[0] * (1.0f / U_NODES) - mu * mu;
        const float a   = gamma[e] * rsqrtf(var + BN_EPS);
        g_ab[e]         = a;
        g_ab[E_DIM + e] = beta[e] - mu * a;
    }
}

// ---------------------------------------------------------------------------
// Kernel 3: out[b] = mean_k tanh(a * h[idx[b,k]] + c), h in fp16
// one warp per output row, uint2 (4 halves) per lane covers the 256B row
// ---------------------------------------------------------------------------
__global__ void __launch_bounds__(128)
gather_mean_kernel(const int* __restrict__ idx, float* __restrict__ out)
{
    __shared__ int sidx[4 * K_SAMP];
    const int b0 = blockIdx.x * 4;
    const int tid = threadIdx.x;
    const int w = tid >> 5;
    const int lane = tid & 31;
    for (int i = tid; i < 4 * K_SAMP; i += 128)
        sidx[i] = idx[b0 * K_SAMP + i];
    __syncthreads();

    const float4 a4 = *(const float4*)&g_ab[lane * 4];
    const float4 c4 = *(const float4*)&g_ab[E_DIM + lane * 4];
    float4 acc = make_float4(0.f, 0.f, 0.f, 0.f);
    const int* myidx = sidx + w * K_SAMP;
#pragma unroll 3
    for (int k = 0; k < K_SAMP; k++) {
        const uint2 u = __ldg((const uint2*)(g_h + (size_t)myidx[k] * E_DIM)
                              + lane);
        const float2 f0 = __half22float2(*(const half2*)&u.x);
        const float2 f1 = __half22float2(*(const half2*)&u.y);
        float t0, t1, t2, t3;
        asm("tanh.approx.f32 %0, %1;" : "=f"(t0) : "f"(fmaf(a4.x, f0.x, c4.x)));
        asm("tanh.approx.f32 %0, %1;" : "=f"(t1) : "f"(fmaf(a4.y, f0.y, c4.y)));
        asm("tanh.approx.f32 %0, %1;" : "=f"(t2) : "f"(fmaf(a4.z, f1.x, c4.z)));
        asm("tanh.approx.f32 %0, %1;" : "=f"(t3) : "f"(fmaf(a4.w, f1.y, c4.w)));
        acc.x += t0; acc.y += t1; acc.z += t2; acc.w += t3;
    }
    const float sc = 1.0f / K_SAMP;
    float4 o = make_float4(acc.x * sc, acc.y * sc, acc.z * sc, acc.w * sc);
    *(float4*)(out + (size_t)(b0 + w) * E_DIM + lane * 4) = o;
}

// ---------------------------------------------------------------------------
extern "C" void kernel_launch(void* const* d_in, const int* in_sizes, int n_in,
                              void* d_out, int out_size)
{
    const float* features = (const float*)d_in[0];
    const float* W        = (const float*)d_in[1];
    const float* bias     = (const float*)d_in[2];
    const float* gamma    = (const float*)d_in[3];
    const float* beta     = (const float*)d_in[4];
    const int*   sidx     = (const int*)d_in[5];
    float*       out      = (float*)d_out;

    cudaFuncSetAttribute(gemm_mma_kernel,
                         cudaFuncAttributeMaxDynamicSharedMemorySize, SMEM_TOTAL);

    prep_w_kernel<<<128, 256>>>(W);
    gemm_mma_kernel<<<NTILES, 256, SMEM_TOTAL>>>(features, bias);
    finalize_stats_kernel<<<128, 256>>>(gamma, beta);
    gather_mean_kernel<<<B_ROWS / 4, 128>>>(sidx, out);
}